// round 3
// baseline (speedup 1.0000x reference)
#include <cuda_runtime.h>
#include <cuda_fp16.h>
#include <cstdint>
#include <cstddef>

#define NN 16384
#define HID 128
#define GG 64

// ---------- static scratch ----------
__device__ __align__(16) uint8_t d_supTf[(NN / 32) * 8192];  // 4 MB: fp16 A fragments
__device__ float d_g[GG * HID];                              // pooled segment-max

// ---------- helpers ----------
__device__ __forceinline__ uint32_t smem_u32(const void* p) {
    uint32_t a;
    asm("{ .reg .u64 t; cvta.to.shared.u64 t, %1; cvt.u32.u64 %0, t; }" : "=r"(a) : "l"(p));
    return a;
}
__device__ __forceinline__ void cp16(uint32_t dst, const void* src) {
    asm volatile("cp.async.cg.shared.global [%0], [%1], 16;" :: "r"(dst), "l"(src) : "memory");
}
#define CP_COMMIT() asm volatile("cp.async.commit_group;" ::: "memory")
#define CP_WAIT(n)  asm volatile("cp.async.wait_group " #n ";" ::: "memory")

__device__ __forceinline__ void lds128(uint32_t* r, uint32_t a) {
    asm volatile("ld.shared.v4.b32 {%0,%1,%2,%3}, [%4];"
                 : "=r"(r[0]), "=r"(r[1]), "=r"(r[2]), "=r"(r[3]) : "r"(a));
}
__device__ __forceinline__ void lds64f(float& x, float& y, uint32_t a) {
    asm volatile("ld.shared.v2.f32 {%0,%1}, [%2];" : "=f"(x), "=f"(y) : "r"(a));
}
__device__ __forceinline__ uint32_t packh2(float lo, float hi) {
    uint32_t d;
    asm("cvt.rn.f16x2.f32 %0, %1, %2;" : "=r"(d) : "f"(hi), "f"(lo));
    return d;
}
__device__ __forceinline__ void mma16816(float* c, const uint32_t* a, const uint32_t* b) {
    asm volatile(
        "mma.sync.aligned.m16n8k16.row.col.f32.f16.f16.f32 "
        "{%0,%1,%2,%3}, {%4,%5,%6,%7}, {%8,%9}, {%0,%1,%2,%3};"
        : "+f"(c[0]), "+f"(c[1]), "+f"(c[2]), "+f"(c[3])
        : "r"(a[0]), "r"(a[1]), "r"(a[2]), "r"(a[3]), "r"(b[0]), "r"(b[1]));
}
__device__ __forceinline__ float leaky(float v) { return v > 0.f ? v : 0.01f * v; }
__device__ __forceinline__ void atomicMaxFloat(float* addr, float v) {
    if (v >= 0.f) atomicMax((int*)addr, __float_as_int(v));
    else          atomicMin((unsigned int*)addr, __float_as_uint(v));
}

// =============== Kernel 1: supT fp16 fragments = (x @ W_gcn)^T ===============
// grid 256: blockIdx -> (node-block of 128, c-half of 64). 128 threads.
#define K1_SMEM (32768 + 64 * 136 * 2)   // ws 32KB + hs 17408B

__global__ void __launch_bounds__(128, 1)
gcn_support(const float* __restrict__ x, const float* __restrict__ Wg)
{
    extern __shared__ char sm1[];
    float4* ws = (float4*)sm1;                 // [128 k][16 float4] (c-half of W)
    __half* hs = (__half*)(sm1 + 32768);       // [64 c][136 nodes] (transposed)
    const int t = threadIdx.x;
    const int bx = blockIdx.x;
    const int mblk = bx >> 1, ch = bx & 1;

    for (int i = t; i < 128 * 16; i += 128) {
        int k = i >> 4, c4 = i & 15;
        ws[i] = ((const float4*)Wg)[k * 32 + ch * 16 + c4];
    }
    if (bx == 0) {
        for (int i = t; i < GG * HID; i += 128)
            d_g[i] = __int_as_float(0xff800000);     // -inf
    }
    __syncthreads();

    const int m = (mblk << 7) + t;
    float acc[64];
    #pragma unroll
    for (int c = 0; c < 64; c++) acc[c] = 0.f;

    const float4* xr = (const float4*)(x + (size_t)m * 128);
    #pragma unroll 1
    for (int k4 = 0; k4 < 32; k4++) {
        float4 xv4 = xr[k4];
        float xs4[4] = {xv4.x, xv4.y, xv4.z, xv4.w};
        #pragma unroll
        for (int kk = 0; kk < 4; kk++) {
            const float xv = xs4[kk];
            const float4* wk = ws + (((k4 << 2) + kk) << 4);
            #pragma unroll
            for (int c4 = 0; c4 < 16; c4++) {
                float4 w = wk[c4];
                acc[4 * c4 + 0] += xv * w.x;
                acc[4 * c4 + 1] += xv * w.y;
                acc[4 * c4 + 2] += xv * w.z;
                acc[4 * c4 + 3] += xv * w.w;
            }
        }
    }
    #pragma unroll
    for (int c = 0; c < 64; c++) hs[c * 136 + t] = __float2half_rn(acc[c]);
    __syncthreads();

    // write fragment-ordered fp16 supT:
    // chunk(=32 nodes) layout: [h16(8)][k16(2)] blocks of 512B = [lane(32)][a0..a3]
    const int lam = t & 31;
    for (int fbi = t >> 5; fbi < 32; fbi += 4) {
        const int cl = fbi >> 3, h16l = (fbi >> 1) & 3, g = fbi & 1;
        uint32_t v[4];
        #pragma unroll
        for (int j = 0; j < 4; j++) {
            int row = h16l * 16 + (lam >> 2) + ((j & 1) << 3);
            int kin = (g << 4) + ((lam & 3) << 1) + ((j >> 1) << 3);
            v[j] = *(const uint32_t*)(hs + row * 136 + cl * 32 + kin);
        }
        const int h16 = ch * 4 + h16l;
        const int chunk = mblk * 4 + cl;
        uint4* dst = (uint4*)(d_supTf + (size_t)chunk * 8192 + (size_t)((h16 * 2 + g) << 9) + (lam << 4));
        *dst = make_uint4(v[0], v[1], v[2], v[3]);
    }
}

// ====== Kernel 2: h^T = supT @ adj^T ; bias + leaky + segment-max (fused) ======
#define STG 4
#define STAGE_BYTES 24576        // A 8KB fp16 frags + B 16KB fp32 adj tile
#define SMEM_K2 (STG * STAGE_BYTES)

__device__ __forceinline__ void load_stage(uint32_t sb, const float* __restrict__ adj,
                                           int m0, int idx, int buf, int tid)
{
    const char* aG = (const char*)d_supTf + (size_t)idx * 8192;
    const uint32_t aS = sb + buf * STAGE_BYTES;
    cp16(aS + tid * 16, aG + tid * 16);
    cp16(aS + (tid + 256) * 16, aG + (tid + 256) * 16);

    const float* bG = adj + (size_t)m0 * NN + idx * 32;
    const uint32_t bS = aS + 8192;
    #pragma unroll
    for (int i = 0; i < 4; i++) {
        int c = tid + (i << 8);                    // 0..1023
        int r = c >> 3, q = c & 7;                 // row, 16B-quad
        uint32_t phys = ((uint32_t)(2 * q)) ^ (uint32_t)((r & 3) << 2);  // 8B-unit swizzle
        cp16(bS + r * 128 + phys * 8, bG + (size_t)r * NN + q * 4);
    }
    CP_COMMIT();
}

__global__ void __launch_bounds__(256, 1)
gcn_gemm_pool(const float* __restrict__ adj, const float* __restrict__ b_gcn,
              const int* __restrict__ batch)
{
    extern __shared__ char smem[];
    const uint32_t sb = smem_u32(smem);
    const int tid = threadIdx.x;
    const int wid = tid >> 5, lid = tid & 31;
    const int wr = wid >> 2, wc = wid & 3;       // 2 x 4 warp grid
    const int m0 = blockIdx.x << 7;

    float acc[4][4][4];
    #pragma unroll
    for (int a = 0; a < 4; a++)
        #pragma unroll
        for (int b = 0; b < 4; b++)
            #pragma unroll
            for (int c = 0; c < 4; c++) acc[a][b][c] = 0.f;

    #pragma unroll
    for (int p = 0; p < STG - 1; p++) load_stage(sb, adj, m0, p, p, tid);

    for (int s = 0; s < 512; s++) {
        if (s < 510)      CP_WAIT(2);
        else if (s == 510) CP_WAIT(1);
        else               CP_WAIT(0);
        __syncthreads();
        if (s + 3 < 512) load_stage(sb, adj, m0, s + 3, (s + 3) & 3, tid);

        const uint32_t aB = sb + (s & 3) * STAGE_BYTES;
        const uint32_t bB = aB + 8192;
        #pragma unroll
        for (int ks = 0; ks < 2; ks++) {
            uint32_t afr[4][4];
            #pragma unroll
            for (int mt = 0; mt < 4; mt++)
                lds128(afr[mt], aB + (uint32_t)((((wr * 4 + mt) * 2 + ks) << 9) + (lid << 4)));
            uint32_t bfr[4][2];
            #pragma unroll
            for (int nt = 0; nt < 4; nt++) {
                int mloc = wc * 32 + nt * 8 + (lid >> 2);
                int u = (lid & 3) + (ks << 3);
                int sw = (mloc & 3) << 2;
                float l0, l1, h0f, h1f;
                lds64f(l0, l1, bB + (uint32_t)(mloc * 128 + ((u ^ sw) << 3)));
                lds64f(h0f, h1f, bB + (uint32_t)(mloc * 128 + (((u + 4) ^ sw) << 3)));
                bfr[nt][0] = packh2(l0, l1);
                bfr[nt][1] = packh2(h0f, h1f);
            }
            #pragma unroll
            for (int mt = 0; mt < 4; mt++)
                #pragma unroll
                for (int nt = 0; nt < 4; nt++)
                    mma16816(acc[mt][nt], afr[mt], bfr[nt]);
        }
    }

    // epilogue: bias + leaky + segment-max (sign-split int atomics)
    #pragma unroll
    for (int nt = 0; nt < 4; nt++) {
        const int mA = m0 + wc * 32 + nt * 8 + 2 * (lid & 3);
        const int g0 = batch[mA] * HID;
        const int g1 = batch[mA + 1] * HID;
        #pragma unroll
        for (int mt = 0; mt < 4; mt++) {
            const int h0 = wr * 64 + mt * 16 + (lid >> 2);
            const float b0v = b_gcn[h0], b8v = b_gcn[h0 + 8];
            atomicMaxFloat(&d_g[g0 + h0],     leaky(acc[mt][nt][0] + b0v));
            atomicMaxFloat(&d_g[g1 + h0],     leaky(acc[mt][nt][1] + b0v));
            atomicMaxFloat(&d_g[g0 + h0 + 8], leaky(acc[mt][nt][2] + b8v));
            atomicMaxFloat(&d_g[g1 + h0 + 8], leaky(acc[mt][nt][3] + b8v));
        }
    }
}

// =============== Kernel 3: tiny MLP + head ===============
__global__ void __launch_bounds__(128)
mlp_head(const float* __restrict__ Wl1, const float* __restrict__ bl1,
         const float* __restrict__ Wl2, const float* __restrict__ bl2,
         const float* __restrict__ Wout, const float* __restrict__ bout,
         float* __restrict__ out)
{
    __shared__ float gin[128], h1[128], h2[128];
    const int i = blockIdx.x, t = threadIdx.x;
    gin[t] = d_g[i * HID + t];
    __syncthreads();

    float a = bl1[t];
    #pragma unroll 4
    for (int k = 0; k < 128; k++) a += gin[k] * Wl1[t * 128 + k];
    h1[t] = leaky(a);
    __syncthreads();

    float b = bl2[t];
    #pragma unroll 4
    for (int k = 0; k < 128; k++) b += h1[k] * Wl2[t * 128 + k];
    h2[t] = leaky(b);
    __syncthreads();

    if (t < 2) {
        float o = bout[t];
        #pragma unroll 4
        for (int k = 0; k < 128; k++) o += h2[k] * Wout[t * 128 + k];
        out[i * 2 + t] = o;
    }
}

// =============== launch ===============
extern "C" void kernel_launch(void* const* d_in, const int* in_sizes, int n_in,
                              void* d_out, int out_size)
{
    const float* x    = (const float*)d_in[0];
    const float* adj  = (const float*)d_in[1];
    const float* Wg   = (const float*)d_in[2];
    const float* bg   = (const float*)d_in[3];
    const float* Wl1  = (const float*)d_in[4];
    const float* bl1  = (const float*)d_in[5];
    const float* Wl2  = (const float*)d_in[6];
    const float* bl2  = (const float*)d_in[7];
    const float* Wout = (const float*)d_in[8];
    const float* bout = (const float*)d_in[9];
    const int*   batch = (const int*)d_in[10];
    float* out = (float*)d_out;

    cudaFuncSetAttribute(gcn_support,   cudaFuncAttributeMaxDynamicSharedMemorySize, K1_SMEM);
    cudaFuncSetAttribute(gcn_gemm_pool, cudaFuncAttributeMaxDynamicSharedMemorySize, SMEM_K2);

    gcn_support<<<256, 128, K1_SMEM>>>(x, Wg);
    gcn_gemm_pool<<<128, 256, SMEM_K2>>>(adj, bg, batch);
    mlp_head<<<GG, 128>>>(Wl1, bl1, Wl2, bl2, Wout, bout, out);
}